// round 2
// baseline (speedup 1.0000x reference)
#include <cuda_runtime.h>
#include <cuda_bf16.h>
#include <cstdint>

// Problem constants
#define NB   8
#define CC   256
#define HH   50
#define WW   68
#define HW   (HH*WW)           // 3400
#define NR   4000
#define SCALE 0.0625f
#define ROWSTRIDE (WW*CC)      // 17408 floats per y-row in NHWC

// NHWC scratch: 8*3400*256 floats = 27.85 MB (static device global, allocation-free)
__device__ float g_nhwc[NB * HW * CC];

// ---------------------------------------------------------------------------
// Kernel 1: NCHW -> NHWC transpose. 32x32 tiles, 256 threads, 4 elems/thread.
// Loads coalesced along p (spatial); stores as float4 along c (channel).
// ---------------------------------------------------------------------------
__global__ __launch_bounds__(256) void nchw_to_nhwc(const float* __restrict__ in) {
    __shared__ float tile[32][33];
    const int b  = blockIdx.z;
    const int c0 = blockIdx.y * 32;  // channel tile base (C=256 -> 8 tiles)
    const int p0 = blockIdx.x * 32;  // spatial tile base  (HW=3400 -> 107 tiles)

    // Load: tx = p-offset (coalesced), 4 c-rows per thread
    const int tx = threadIdx.x & 31;
    const int ty = threadIdx.x >> 5;         // 0..7
    const int p  = p0 + tx;
    if (p < HW) {
        #pragma unroll
        for (int k = 0; k < 4; k++) {
            int c = c0 + ty + k * 8;
            tile[ty + k * 8][tx] = in[((size_t)b * CC + c) * HW + p];
        }
    }
    __syncthreads();

    // Store: one float4 along c per thread. thread -> (p = tid/8, cg = tid%8)
    const int sp = threadIdx.x >> 3;         // 0..31
    const int cg = threadIdx.x & 7;          // 0..7  (c group of 4)
    const int pp = p0 + sp;
    if (pp < HW) {
        float4 v;
        v.x = tile[cg * 4 + 0][sp];
        v.y = tile[cg * 4 + 1][sp];
        v.z = tile[cg * 4 + 2][sp];
        v.w = tile[cg * 4 + 3][sp];
        *reinterpret_cast<float4*>(
            &g_nhwc[((size_t)b * HW + pp) * CC + c0 + cg * 4]) = v;
    }
}

// ---------------------------------------------------------------------------
// Kernel 2: RoIAlign (aligned avg). One CTA per roi, one thread per channel.
// Gathers are warp-coalesced 128B lines out of NHWC (L2-resident).
// Output staged ONE POOLED ROW at a time (7KB, double-buffered) so smem stays
// tiny -> occupancy is register-limited, not smem-limited.
// ---------------------------------------------------------------------------
__global__ __launch_bounds__(256, 5) void roi_align_kernel(
    const float* __restrict__ rois, float* __restrict__ out)
{
    __shared__ float s_row[2][CC * 7];   // 2 x 7168 B

    const int r = blockIdx.x;
    const int c = threadIdx.x;

    const float* roi = rois + r * 5;
    const int   bi = (int)roi[0];
    const float x1 = roi[1] * SCALE;
    const float y1 = roi[2] * SCALE;
    const float x2 = roi[3] * SCALE;
    const float y2 = roi[4] * SCALE;
    const float bin_w = fmaxf(x2 - x1, 0.0f) * (1.0f / 7.0f);
    const float bin_h = fmaxf(y2 - y1, 0.0f) * (1.0f / 7.0f);

    // x-axis geometry for the 8 sample columns
    int   xoff[8];
    float lxv[8];
    float mxv[8];
    #pragma unroll
    for (int pw = 0; pw < 8; pw++) {
        float w  = x1 + (float)pw * bin_w;
        mxv[pw]  = (w >= 0.0f && w < (float)WW) ? 1.0f : 0.0f;
        float xf = fminf(fmaxf(floorf(w), 0.0f), (float)(WW - 2));
        lxv[pw]  = w - xf;
        xoff[pw] = (int)xf * CC;
    }

    const float* fbase = g_nhwc + (size_t)bi * HW * CC + c;
    float* const  obase = out + (size_t)r * (CC * 49);

    float prev[8];
    #pragma unroll
    for (int sph = 0; sph < 8; sph++) {
        float h  = y1 + (float)sph * bin_h;
        float my = (h >= 0.0f && h < (float)HH) ? 1.0f : 0.0f;
        float yf = fminf(fmaxf(floorf(h), 0.0f), (float)(HH - 2));
        float ly = h - yf;
        const float* r0 = fbase + (int)yf * ROWSTRIDE;
        const float* r1 = r0 + ROWSTRIDE;

        float s[8];
        #pragma unroll
        for (int pw = 0; pw < 8; pw++) {
            float v00 = __ldg(r0 + xoff[pw]);
            float v01 = __ldg(r0 + xoff[pw] + CC);
            float v10 = __ldg(r1 + xoff[pw]);
            float v11 = __ldg(r1 + xoff[pw] + CC);
            float top = fmaf(lxv[pw], v01 - v00, v00);
            float bot = fmaf(lxv[pw], v11 - v10, v10);
            float val = fmaf(ly, bot - top, top);
            s[pw] = val * (my * mxv[pw]);
        }

        if (sph > 0) {
            const int i   = sph - 1;            // pooled output row index
            const int buf = i & 1;
            // produce pooled row i into smem (bank-conflict-free: stride 7)
            #pragma unroll
            for (int pw = 0; pw < 7; pw++) {
                s_row[buf][c * 7 + pw] =
                    0.25f * ((prev[pw] + prev[pw + 1]) + (s[pw] + s[pw + 1]));
            }
            __syncthreads();
            // copy row i to global: linear j -> mostly-contiguous 28B runs
            float* orow = obase + i * 7;
            #pragma unroll
            for (int k = 0; k < 7; k++) {
                int j  = c + k * CC;            // 0..1791
                int ch = j / 7;
                int pw = j - ch * 7;
                orow[ch * 49 + pw] = s_row[buf][j];
            }
            // next write to this buffer happens after the NEXT sync -> safe
        }
        #pragma unroll
        for (int pw = 0; pw < 8; pw++) prev[pw] = s[pw];
    }
}

// ---------------------------------------------------------------------------
extern "C" void kernel_launch(void* const* d_in, const int* in_sizes, int n_in,
                              void* d_out, int out_size)
{
    const float* features = (const float*)d_in[0];  // [8,256,50,68]
    const float* rois     = (const float*)d_in[1];  // [4000,5]
    float*       out      = (float*)d_out;          // [4000,256,7,7]

    dim3 tg((HW + 31) / 32, CC / 32, NB);
    nchw_to_nhwc<<<tg, 256>>>(features);

    roi_align_kernel<<<NR, CC>>>(rois, out);
}